// round 14
// baseline (speedup 1.0000x reference)
#include <cuda_runtime.h>
#include <cstdint>

// Binarize: x[4096, 8192] fp32, depth[3] -> out[4096, 3, 1024] float32,
// each output element = numeric value of the big-endian packed byte.
//
// R14: one-shot variant of the R7 champion. Same memory structure
// (8 consecutive floats/thread = 32B lane stride, .cs loads, .cg stores so
// the 50MB output stays L2-resident across graph replays, float-accumulation
// pack on the fma pipe), but NO grid-stride loop: 16384 CTAs x 256 threads,
// exactly one chunk per thread. Removes loop compare/branch, pipeline
// register copies, and the 13-vs-14-iteration thread raggedness; tail
// balancing happens at CTA granularity via the hardware scheduler.

#define COLS 8192
#define BPR  (COLS / 8)     // 1024 packed bytes (output floats) per row per plane

__global__ __launch_bounds__(256) void binarize_kernel(
    const float* __restrict__ x,
    const float* __restrict__ depth,
    float* __restrict__ out)
{
    const int c = blockIdx.x * blockDim.x + threadIdx.x;  // chunk index

    const float d0 = __ldg(depth + 0);
    const float d1 = __ldg(depth + 1);
    const float d2 = __ldg(depth + 2);

    const float4* __restrict__ x4 = reinterpret_cast<const float4*>(x);
    const float4 a = __ldcs(x4 + 2 * (size_t)c);
    const float4 b = __ldcs(x4 + 2 * (size_t)c + 1);

    // Pack via float accumulation (fma pipe). Big-endian: weight 2^(7-e).
    const float f[8] = { a.x, a.y, a.z, a.w, b.x, b.y, b.z, b.w };
    float a0 = 0.0f, a1 = 0.0f, a2 = 0.0f;
#pragma unroll
    for (int e = 0; e < 8; e++) {
        const float w = (float)(1u << (7 - e));   // compile-time constant
        if (f[e] > d0) a0 += w;
        if (f[e] > d1) a1 += w;
        if (f[e] > d2) a2 += w;
    }

    const int row = c >> 10;           // c / BPR
    const int t   = c & (BPR - 1);
    float* o = out + (size_t)row * (3 * BPR) + t;
    __stcg(o,           a0);
    __stcg(o + BPR,     a1);
    __stcg(o + 2 * BPR, a2);
}

extern "C" void kernel_launch(void* const* d_in, const int* in_sizes, int n_in,
                              void* d_out, int out_size) {
    const float* x     = (const float*)d_in[0];
    const float* depth = (const float*)d_in[1];
    float*       out   = (float*)d_out;

    const int n       = in_sizes[0];   // 4096 * 8192
    const int nchunks = n / 8;         // 4,194,304 (multiple of 256)

    const int block = 256;
    const int grid  = nchunks / block; // 16384 one-shot CTAs

    binarize_kernel<<<grid, block>>>(x, depth, out);
}